// round 11
// baseline (speedup 1.0000x reference)
#include <cuda_runtime.h>
#include <cstdint>

// CTC greedy decode:  probs [B, T=512, C=128] f32  ->  out [B, T] (float32 values)
//
// R8 : one-CTA-per-row, REDUX argmax -> 45.6us, DRAM 76%, occ 80% (grid-bound!)
// R9 : batch4+ldcs FAILED (occ 61%). R10: batch2 NEUTRAL (73% DRAM).
// R11: two-kernel split. K1 = grid-stride argmax over all B*T timesteps with
//      grid 1184x256 (fills every warp slot on 148 SMs; no smem/sync/tail),
//      ballot tie-break (single REDUX). K2 = decode+pack from 2MB scratch.

#define CTC_T 512
#define CTC_C 128
#define CTC_BLANK (CTC_C - 1)
#define CTC_THREADS 256
#define CTC_WARPS (CTC_THREADS / 32)
#define MAX_BT (1024 * 512)           // scratch capacity (timesteps)
#define K1_GRID (148 * 8)             // full-chip slot count at 256 thr/CTA

__device__ int g_best[MAX_BT];

// Order-preserving float->uint map (monotone for all finite floats).
__device__ __forceinline__ unsigned f2ord(float f) {
    unsigned u = __float_as_uint(f);
    return (u & 0x80000000u) ? ~u : (u | 0x80000000u);
}

// ---------------- Kernel 1: streaming argmax, one warp per timestep ----------------
template<bool VEC4>
__global__ __launch_bounds__(CTC_THREADS)
void ctc_argmax_kernel(const float* __restrict__ probs,
                       int* __restrict__ best_out,
                       long long n_ts)
{
    const int  lane = threadIdx.x & 31;
    const long long w0      = (long long)blockIdx.x * CTC_WARPS + (threadIdx.x >> 5);
    const long long wstride = (long long)gridDim.x * CTC_WARPS;

    for (long long t = w0; t < n_ts; t += wstride) {
        float m;
        int   mi;
        if (VEC4) {
            const float4 v = __ldg(reinterpret_cast<const float4*>(probs + t * CTC_C) + lane);
            m  = v.x;  mi = lane * 4;
            if (v.y > m) { m = v.y; mi = lane * 4 + 1; }
            if (v.z > m) { m = v.z; mi = lane * 4 + 2; }
            if (v.w > m) { m = v.w; mi = lane * 4 + 3; }
        } else {
            const float* row = probs + t * CTC_C;
            m  = __ldg(row + lane);  mi = lane;
            #pragma unroll
            for (int k = 1; k < 4; ++k) {
                const int   c = lane + k * 32;
                const float v = __ldg(row + c);
                if (v > m) { m = v; mi = c; }
            }
        }
        // Warp argmax: REDUX max over order-mapped values, then lowest lane
        // holding the max (lane index ranges are disjoint & ascending, so the
        // lowest max-holding lane owns the lowest tying class index).
        const unsigned mo   = f2ord(m);
        const unsigned vmax = __reduce_max_sync(0xffffffffu, mo);
        const unsigned ball = __ballot_sync(0xffffffffu, mo == vmax);
        if ((mo == vmax) && ((ball & ((1u << lane) - 1u)) == 0u))
            best_out[t] = mi;
    }
}

// ---------------- Kernel 2: decode + left-pack, one CTA per row ----------------
__global__ __launch_bounds__(CTC_THREADS)
void ctc_pack_kernel(const int* __restrict__ best_in,
                     const int* __restrict__ table,
                     const int* __restrict__ defc_ptr,
                     float* __restrict__ out)
{
    __shared__ int   s_best[CTC_T];
    __shared__ int   s_wsum[CTC_WARPS];
    __shared__ float s_table[CTC_C];

    const int b    = blockIdx.x;
    const int tid  = threadIdx.x;
    const int lane = tid & 31;
    const int wid  = tid >> 5;

    if (tid < CTC_C) s_table[tid] = (float)table[tid];

    const int* __restrict__ brow = best_in + (size_t)b * CTC_T;
    s_best[tid]              = __ldg(brow + tid);
    s_best[tid + CTC_THREADS] = __ldg(brow + tid + CTC_THREADS);
    __syncthreads();

    // thread owns timesteps 2t, 2t+1
    const int t0 = 2 * tid, t1 = 2 * tid + 1;
    const int b0 = s_best[t0];
    const int b1 = s_best[t1];
    const int p0 = (t0 == 0) ? -1 : s_best[t0 - 1];
    const int v0 = (b0 != p0 && b0 != CTC_BLANK) ? 1 : 0;
    const int v1 = (b1 != b0 && b1 != CTC_BLANK) ? 1 : 0;
    const int pair = v0 + v1;

    int x = pair;
    #pragma unroll
    for (int off = 1; off < 32; off <<= 1) {
        int y = __shfl_up_sync(0xffffffffu, x, off);
        if (lane >= off) x += y;
    }
    if (lane == 31) s_wsum[wid] = x;
    __syncthreads();

    if (wid == 0) {
        int ws = (lane < CTC_WARPS) ? s_wsum[lane] : 0;
        #pragma unroll
        for (int off = 1; off < CTC_WARPS; off <<= 1) {
            int y = __shfl_up_sync(0xffffffffu, ws, off);
            if (lane >= off) ws += y;
        }
        if (lane < CTC_WARPS) s_wsum[lane] = ws;
    }
    __syncthreads();

    const int incl_pair = x + (wid > 0 ? s_wsum[wid - 1] : 0);
    const int excl      = incl_pair - pair;
    const int count     = s_wsum[CTC_WARPS - 1];
    const float defc    = defc_ptr ? (float)__ldg(defc_ptr) : 32.0f;

    float* __restrict__ orow = out + (size_t)b * CTC_T;
    if (v0) orow[excl]        = s_table[b0];
    if (v1) orow[excl + v0]   = s_table[b1];
    if (t0 >= count) orow[t0] = defc;
    if (t1 >= count) orow[t1] = defc;
}

// ---------------- Fallback: proven R8 single-kernel (for oversize B) ----------------
template<bool VEC4>
__global__ __launch_bounds__(CTC_THREADS)
void ctc_decode_fused(const float* __restrict__ probs,
                      const int* __restrict__ table,
                      const int* __restrict__ defc_ptr,
                      float* __restrict__ out,
                      long long n_probs_elems)
{
    __shared__ int   s_best[CTC_T];
    __shared__ int   s_wsum[CTC_WARPS];
    __shared__ float s_table[CTC_C];

    const int b    = blockIdx.x;
    const int tid  = threadIdx.x;
    const int lane = tid & 31;
    const int wid  = tid >> 5;

    if ((long long)(b + 1) * CTC_T * CTC_C > n_probs_elems) return;
    if (tid < CTC_C) s_table[tid] = (float)table[tid];

    const float* __restrict__ base = probs + (size_t)b * CTC_T * CTC_C;

    #pragma unroll 4
    for (int t = wid; t < CTC_T; t += CTC_WARPS) {
        float m; int mi;
        if (VEC4) {
            const float4 v = __ldg(reinterpret_cast<const float4*>(base + t * CTC_C) + lane);
            m  = v.x;  mi = lane * 4;
            if (v.y > m) { m = v.y; mi = lane * 4 + 1; }
            if (v.z > m) { m = v.z; mi = lane * 4 + 2; }
            if (v.w > m) { m = v.w; mi = lane * 4 + 3; }
        } else {
            const float* row = base + t * CTC_C;
            m  = __ldg(row + lane);  mi = lane;
            #pragma unroll
            for (int k = 1; k < 4; ++k) {
                const int   c = lane + k * 32;
                const float v = __ldg(row + c);
                if (v > m) { m = v; mi = c; }
            }
        }
        const unsigned mo   = f2ord(m);
        const unsigned vmax = __reduce_max_sync(0xffffffffu, mo);
        const unsigned ball = __ballot_sync(0xffffffffu, mo == vmax);
        if ((mo == vmax) && ((ball & ((1u << lane) - 1u)) == 0u)) s_best[t] = mi;
    }
    __syncthreads();

    const int t0 = 2 * tid, t1 = 2 * tid + 1;
    const int b0 = s_best[t0];
    const int b1 = s_best[t1];
    const int p0 = (t0 == 0) ? -1 : s_best[t0 - 1];
    const int v0 = (b0 != p0 && b0 != CTC_BLANK) ? 1 : 0;
    const int v1 = (b1 != b0 && b1 != CTC_BLANK) ? 1 : 0;
    const int pair = v0 + v1;

    int x = pair;
    #pragma unroll
    for (int off = 1; off < 32; off <<= 1) {
        int y = __shfl_up_sync(0xffffffffu, x, off);
        if (lane >= off) x += y;
    }
    if (lane == 31) s_wsum[wid] = x;
    __syncthreads();
    if (wid == 0) {
        int ws = (lane < CTC_WARPS) ? s_wsum[lane] : 0;
        #pragma unroll
        for (int off = 1; off < CTC_WARPS; off <<= 1) {
            int y = __shfl_up_sync(0xffffffffu, ws, off);
            if (lane >= off) ws += y;
        }
        if (lane < CTC_WARPS) s_wsum[lane] = ws;
    }
    __syncthreads();

    const int incl_pair = x + (wid > 0 ? s_wsum[wid - 1] : 0);
    const int excl      = incl_pair - pair;
    const int count     = s_wsum[CTC_WARPS - 1];
    const float defc    = defc_ptr ? (float)__ldg(defc_ptr) : 32.0f;

    float* __restrict__ orow = out + (size_t)b * CTC_T;
    if (v0) orow[excl]        = s_table[b0];
    if (v1) orow[excl + v0]   = s_table[b1];
    if (t0 >= count) orow[t0] = defc;
    if (t1 >= count) orow[t1] = defc;
}

extern "C" void kernel_launch(void* const* d_in, const int* in_sizes, int n_in,
                              void* d_out, int out_size)
{
    // --- bind inputs by size (elements-vs-bytes auto-detected) ---
    int probs_i = 0;
    long long max_sz = -1;
    for (int i = 0; i < n_in; ++i)
        if ((long long)in_sizes[i] > max_sz) { max_sz = in_sizes[i]; probs_i = i; }

    int table_i = -1, defc_i = -1;
    int scale = 1;
    for (int i = 0; i < n_in; ++i) {
        if (i == probs_i) continue;
        const int s = in_sizes[i];
        if (s == CTC_C)                          { table_i = i; scale = 1; }
        else if (s == CTC_C * 4 && table_i < 0)  { table_i = i; scale = 4; }
        else if (s == 1 || s == 4)               { if (defc_i < 0) defc_i = i; }
    }
    if (table_i < 0) { table_i = (probs_i == 0 && n_in > 1) ? 1 : 0; scale = 1; }

    const float* probs = (const float*)d_in[probs_i];
    const int*   table = (const int*)d_in[table_i];
    const int*   defc  = (defc_i >= 0) ? (const int*)d_in[defc_i] : nullptr;
    float*       out   = (float*)d_out;

    const long long probs_elems = max_sz / scale;
    const int B = (int)(probs_elems / ((long long)CTC_T * CTC_C));
    if (B <= 0) return;

    const long long n_ts = (long long)B * CTC_T;
    const bool aligned16 = ((uintptr_t)probs & 15u) == 0;

    if (n_ts <= MAX_BT) {
        int* best = nullptr;
        cudaGetSymbolAddress((void**)&best, g_best);
        const int grid1 = (n_ts < (long long)K1_GRID * CTC_WARPS)
                        ? (int)((n_ts + CTC_WARPS - 1) / CTC_WARPS) : K1_GRID;
        if (aligned16)
            ctc_argmax_kernel<true ><<<grid1, CTC_THREADS>>>(probs, best, n_ts);
        else
            ctc_argmax_kernel<false><<<grid1, CTC_THREADS>>>(probs, best, n_ts);
        ctc_pack_kernel<<<B, CTC_THREADS>>>(best, table, defc, out);
    } else {
        if (aligned16)
            ctc_decode_fused<true ><<<B, CTC_THREADS>>>(probs, table, defc, out, probs_elems);
        else
            ctc_decode_fused<false><<<B, CTC_THREADS>>>(probs, table, defc, out, probs_elems);
    }
}

// round 12
// speedup vs baseline: 1.2699x; 1.2699x over previous
#include <cuda_runtime.h>
#include <cstdint>

// CTC greedy decode:  probs [B, T=512, C=128] f32  ->  out [B, T] (float32 values)
// best[t] = argmax_c probs[b,t,c] (first-max tie-break, like jnp.argmax)
// valid[t] = best[t] != best[t-1] (prev=-1 at t=0)  &&  best[t] != C-1 (blank)
// out row  = table[best] for valid t (left-packed), tail = default_char.
//
// History: R8 (one CTA/row, 256thr, REDUX argmax) = 45.6us, DRAM 76% -- best.
// R9 (batch4+ldcs), R10 (batch2+launch_bounds), R11 (two-kernel grid-stride)
// all regressed => 76% DRAM is this pattern's service ceiling; occupancy and
// per-warp MLP are not binding. R12 = exact R8 structure + ballot tie-break
// (VEC4 path only; lane->class ranges are monotone there).

#define CTC_T 512
#define CTC_C 128
#define CTC_BLANK (CTC_C - 1)
#define CTC_THREADS 256
#define CTC_WARPS (CTC_THREADS / 32)

// Order-preserving float->uint map (monotone for all finite floats).
__device__ __forceinline__ unsigned f2ord(float f) {
    unsigned u = __float_as_uint(f);
    return (u & 0x80000000u) ? ~u : (u | 0x80000000u);
}

template<bool VEC4>
__global__ __launch_bounds__(CTC_THREADS)
void ctc_decode_kernel(const float* __restrict__ probs,
                       const int* __restrict__ table,
                       const int* __restrict__ defc_ptr,
                       float* __restrict__ out,
                       long long n_probs_elems)
{
    __shared__ int   s_best[CTC_T];
    __shared__ int   s_wsum[CTC_WARPS];
    __shared__ float s_table[CTC_C];

    const int b    = blockIdx.x;
    const int tid  = threadIdx.x;
    const int lane = tid & 31;
    const int wid  = tid >> 5;

    // Bounds guard: never read past the probs buffer.
    if ((long long)(b + 1) * CTC_T * CTC_C > n_probs_elems) return;

    if (tid < CTC_C) s_table[tid] = (float)table[tid];

    const float* __restrict__ base = probs + (size_t)b * CTC_T * CTC_C;

    // ---- Phase 1: per-timestep argmax, one warp per timestep ----
    // Warp `wid` handles t = wid, wid+8, ... (consecutive warps -> contiguous
    // 4KB per pass). Lane-local 4-way argmax, then warp argmax.
    #pragma unroll 4
    for (int t = wid; t < CTC_T; t += CTC_WARPS) {
        if (VEC4) {
            const float4 v = __ldg(reinterpret_cast<const float4*>(base + t * CTC_C) + lane);
            float m  = v.x;  int mi = lane * 4;
            if (v.y > m) { m = v.y; mi = lane * 4 + 1; }
            if (v.z > m) { m = v.z; mi = lane * 4 + 2; }
            if (v.w > m) { m = v.w; mi = lane * 4 + 3; }
            // REDUX max over order-mapped values; lowest max-holding lane wins
            // the tie (lane->class ranges are monotone in this path, so the
            // lowest lane owns the lowest tying class index, per jnp.argmax).
            const unsigned mo   = f2ord(m);
            const unsigned vmax = __reduce_max_sync(0xffffffffu, mo);
            const unsigned ball = __ballot_sync(0xffffffffu, mo == vmax);
            if ((mo == vmax) && ((ball & ((1u << lane) - 1u)) == 0u))
                s_best[t] = mi;
        } else {
            // Coalesced scalar fallback (unaligned probs pointer). Lane->class
            // ranges are interleaved here, so use REDUX min-index tie-break.
            const float* row = base + t * CTC_C;
            float m  = __ldg(row + lane);  int mi = lane;
            #pragma unroll
            for (int k = 1; k < 4; ++k) {
                const int   c = lane + k * 32;
                const float v = __ldg(row + c);
                if (v > m) { m = v; mi = c; }
            }
            const unsigned mo   = f2ord(m);
            const unsigned vmax = __reduce_max_sync(0xffffffffu, mo);
            const unsigned cand = (mo == vmax) ? (unsigned)mi : 0xffffffffu;
            const unsigned imin = __reduce_min_sync(0xffffffffu, cand);
            if (lane == 0) s_best[t] = (int)imin;
        }
    }
    __syncthreads();

    // ---- Phase 2: valid flags + block scan; thread owns timesteps 2t, 2t+1 ----
    const int t0 = 2 * tid, t1 = 2 * tid + 1;
    const int b0 = s_best[t0];
    const int b1 = s_best[t1];
    const int p0 = (t0 == 0) ? -1 : s_best[t0 - 1];
    const int v0 = (b0 != p0 && b0 != CTC_BLANK) ? 1 : 0;
    const int v1 = (b1 != b0 && b1 != CTC_BLANK) ? 1 : 0;
    const int pair = v0 + v1;

    int x = pair;
    #pragma unroll
    for (int off = 1; off < 32; off <<= 1) {
        int y = __shfl_up_sync(0xffffffffu, x, off);
        if (lane >= off) x += y;
    }
    if (lane == 31) s_wsum[wid] = x;
    __syncthreads();

    if (wid == 0) {
        int ws = (lane < CTC_WARPS) ? s_wsum[lane] : 0;
        #pragma unroll
        for (int off = 1; off < CTC_WARPS; off <<= 1) {
            int y = __shfl_up_sync(0xffffffffu, ws, off);
            if (lane >= off) ws += y;
        }
        if (lane < CTC_WARPS) s_wsum[lane] = ws;
    }
    __syncthreads();

    const int incl_pair = x + (wid > 0 ? s_wsum[wid - 1] : 0); // inclusive over pairs
    const int excl      = incl_pair - pair;                     // exclusive before t0
    const int count     = s_wsum[CTC_WARPS - 1];                // total valid in row
    const float defc    = defc_ptr ? (float)__ldg(defc_ptr) : 32.0f;

    float* __restrict__ orow = out + (size_t)b * CTC_T;
    if (v0) orow[excl]        = s_table[b0];   // packed positions
    if (v1) orow[excl + v0]   = s_table[b1];
    if (t0 >= count) orow[t0] = defc;          // tail padding (disjoint)
    if (t1 >= count) orow[t1] = defc;
}

extern "C" void kernel_launch(void* const* d_in, const int* in_sizes, int n_in,
                              void* d_out, int out_size)
{
    // --- bind inputs by size (elements-vs-bytes auto-detected) ---
    int probs_i = 0;
    long long max_sz = -1;
    for (int i = 0; i < n_in; ++i)
        if ((long long)in_sizes[i] > max_sz) { max_sz = in_sizes[i]; probs_i = i; }

    int table_i = -1, defc_i = -1;
    int scale = 1;
    for (int i = 0; i < n_in; ++i) {
        if (i == probs_i) continue;
        const int s = in_sizes[i];
        if (s == CTC_C)                          { table_i = i; scale = 1; }
        else if (s == CTC_C * 4 && table_i < 0)  { table_i = i; scale = 4; }
        else if (s == 1 || s == 4)               { if (defc_i < 0) defc_i = i; }
    }
    if (table_i < 0) { table_i = (probs_i == 0 && n_in > 1) ? 1 : 0; scale = 1; }

    const float* probs = (const float*)d_in[probs_i];
    const int*   table = (const int*)d_in[table_i];
    const int*   defc  = (defc_i >= 0) ? (const int*)d_in[defc_i] : nullptr;
    float*       out   = (float*)d_out;

    const long long probs_elems = max_sz / scale;
    const int B = (int)(probs_elems / ((long long)CTC_T * CTC_C));
    if (B <= 0) return;

    const bool aligned16 = ((uintptr_t)probs & 15u) == 0;
    if (aligned16)
        ctc_decode_kernel<true ><<<B, CTC_THREADS>>>(probs, table, defc, out, probs_elems);
    else
        ctc_decode_kernel<false><<<B, CTC_THREADS>>>(probs, table, defc, out, probs_elems);
}